// round 7
// baseline (speedup 1.0000x reference)
#include <cuda_runtime.h>
#include <cuda_fp16.h>
#include <stdint.h>

#define NB 32
#define NC 8
#define NL 2048
#define NK 512
#define NS 64
#define NW (NL - NS + 1)   // 1985
#define NWP 2048           // padded inv row
#define KTOT 512           // NC * NS

// ---------------- device scratch (static, allocation-free) ----------------
__device__ __half g_B[(size_t)NK * KTOT];          // 512 KB, [k][c*64+s]
__device__ float  g_inv[(size_t)NB * NC * NWP];    // 2 MB, zero-padded w>=NW

// ---------------- helpers ----------------
__device__ __forceinline__ uint32_t smem_u32(const void* p) {
    uint32_t a;
    asm("{ .reg .u64 t; cvta.to.shared.u64 t, %1; cvt.u32.u64 %0, t; }"
        : "=r"(a) : "l"(p));
    return a;
}

__device__ __forceinline__ void cp16(uint32_t dst, const void* src) {
    asm volatile("cp.async.cg.shared.global [%0], [%1], 16;" :: "r"(dst), "l"(src));
}

__device__ __forceinline__ void cp16z(uint32_t dst, const void* src, uint32_t sz) {
    asm volatile("cp.async.cg.shared.global [%0], [%1], 16, %2;"
                 :: "r"(dst), "l"(src), "r"(sz));
}

__device__ __forceinline__ void ldsm4(uint32_t* r, uint32_t addr) {
    asm volatile("ldmatrix.sync.aligned.m8n8.x4.shared.b16 {%0,%1,%2,%3}, [%4];"
                 : "=r"(r[0]), "=r"(r[1]), "=r"(r[2]), "=r"(r[3]) : "r"(addr));
}

__device__ __forceinline__ void mma16816(float* d, const uint32_t* a, const uint32_t* b) {
    asm volatile(
        "mma.sync.aligned.m16n8k16.row.col.f32.f16.f16.f32 "
        "{%0,%1,%2,%3}, {%4,%5,%6,%7}, {%8,%9}, {%0,%1,%2,%3};"
        : "+f"(d[0]), "+f"(d[1]), "+f"(d[2]), "+f"(d[3])
        : "r"(a[0]), "r"(a[1]), "r"(a[2]), "r"(a[3]), "r"(b[0]), "r"(b[1]));
}

// ---------------- Kernel 1: fused prep (B fp16 + padded window inv-norms) --
__global__ __launch_bounds__(256) void prep_kernel(const float* __restrict__ x,
                                                   const float* __restrict__ sh) {
    if (blockIdx.x < 512) {
        int gw   = (blockIdx.x * 256 + threadIdx.x) >> 5;
        int lane = threadIdx.x & 31;
        int c = gw / NK, k = gw % NK;
        const float* row = sh + (size_t)(c * NK + k) * NS;
        float v0 = row[lane], v1 = row[lane + 32];
        float ss = v0 * v0 + v1 * v1;
        #pragma unroll
        for (int o = 16; o > 0; o >>= 1) ss += __shfl_xor_sync(0xffffffffu, ss, o);
        float sc = 0.125f / fmaxf(sqrtf(ss), 1e-8f);
        size_t base = (size_t)k * KTOT + c * 64 + lane;
        g_B[base]      = __float2half(v0 * sc);
        g_B[base + 32] = __float2half(v1 * sc);
    } else {
        __shared__ float xs[NL];
        int bc = blockIdx.x - 512;
        const float* row = x + (size_t)bc * NL;
        for (int i = threadIdx.x; i < NL; i += 256) xs[i] = row[i];
        __syncthreads();
        for (int w = threadIdx.x; w < NWP; w += 256) {
            float r = 0.f;
            if (w < NW) {
                float ss = 0.f;
                #pragma unroll 16
                for (int s = 0; s < NS; ++s) { float v = xs[w + s]; ss += v * v; }
                r = 1.0f / fmaxf(sqrtf(ss), 1e-8f);
            }
            g_inv[(size_t)bc * NWP + w] = r;
        }
    }
}

// ---------------- Kernel 2: fused im2col + fp16 GEMM + relu-max ------------
// Block tile M=128 x N=256, 512 threads (16 warps, 4x4), warp tile 32x64.
// Per stage: cp.async B (32 KB) + raw x slice (768 B) + inv (512 B);
// A(cc+1) converted into swizzled fp16 smem overlapped with MMAs of cc.
#define ST_STRIDE 50432
#define OFF_B 16384
#define OFF_X 49152
#define OFF_INV 49920
#define SMEM_BYTES (3 * ST_STRIDE)   // 151296

__global__ __launch_bounds__(512, 1) void gemm_kernel(const float* __restrict__ x,
                                                      float* __restrict__ out) {
    extern __shared__ char smem[];
    const uint32_t sb = smem_u32(smem);
    const int tid = threadIdx.x;
    const int wid = tid >> 5, lane = tid & 31;
    const int m0 = blockIdx.x * 128, n0 = blockIdx.y * 256, b = blockIdx.z;

    const int wm = wid & 3, wn = wid >> 2;   // 4 x 4 warp grid

    const int t8 = lane >> 3, lr = lane & 7;
    const int arow = wm * 32 + (t8 & 1) * 8 + lr;   // + i*16, i<2
    const int achk = t8 >> 1;                        // + 2*ks
    const int brow = wn * 64 + (t8 >> 1) * 8 + lr;  // + p*16, p<4
    const int bchk = t8 & 1;                         // + 2*ks
    const int arow7 = arow & 7, brow7 = brow & 7;
    const uint32_t aRowB0 = (uint32_t)(arow * 128);
    const uint32_t bRowB0 = (uint32_t)(brow * 128);

    const __half* B0 = g_B + (size_t)n0 * KTOT;
    const float*  xrow_base = x + (size_t)(b * NC) * NL;
    const float*  irow_base = g_inv + (size_t)(b * NC) * NWP;

    // stage loader: B 256x64 fp16 (swizzled) + raw x slice + inv slice
    auto load_stage = [&](int cc, int s) {
        const uint32_t base = sb + s * ST_STRIDE;
        const __half* gb = B0 + cc * 64;
        #pragma unroll
        for (int j = 0; j < 4; ++j) {        // B: 2048 chunks / 512 thr
            int i = j * 512 + tid;
            int row = i >> 3, c16 = i & 7;
            uint32_t so = (uint32_t)(row * 128 + ((c16 ^ (row & 7)) << 4));
            cp16(base + OFF_B + so, gb + (size_t)row * KTOT + c16 * 8);
        }
        if (tid < 48) {                       // x slice: 192 floats
            int off = m0 + tid * 4;
            cp16z(base + OFF_X + tid * 16, xrow_base + (size_t)cc * NL + off,
                  off < NL ? 16u : 0u);
        } else if (tid < 80) {                // inv slice: 128 floats (padded src)
            int ch = tid - 48;
            cp16(base + OFF_INV + ch * 16,
                 irow_base + (size_t)cc * NWP + m0 + ch * 4);
        }
        asm volatile("cp.async.commit_group;");
    };

    // convert raw x slice of stage s into swizzled fp16 A tile of stage s
    auto convert_A = [&](int s) {
        const float* fx  = reinterpret_cast<const float*>(smem + s * ST_STRIDE + OFF_X);
        const float* fin = reinterpret_cast<const float*>(smem + s * ST_STRIDE + OFF_INV);
        char* abase = smem + s * ST_STRIDE;
        #pragma unroll
        for (int it = 0; it < 2; ++it) {
            int idx = it * 512 + tid;         // 1024 16B-chunks: 128 rows x 8
            int r = idx >> 3, c16 = idx & 7;
            float inv = fin[r];
            __half h[8];
            #pragma unroll
            for (int j = 0; j < 8; ++j)
                h[j] = __float2half(fx[r + c16 * 8 + j] * inv);
            uint32_t so = (uint32_t)(r * 128 + ((c16 ^ (r & 7)) << 4));
            *reinterpret_cast<uint4*>(abase + so) = *reinterpret_cast<uint4*>(h);
        }
    };

    float acc[2][8][4];
    #pragma unroll
    for (int i = 0; i < 2; ++i)
        #pragma unroll
        for (int j = 0; j < 8; ++j)
            #pragma unroll
            for (int c = 0; c < 4; ++c) acc[i][j][c] = 0.f;

    load_stage(0, 0);
    load_stage(1, 1);
    asm volatile("cp.async.wait_group 1;");
    __syncthreads();                  // raw0 visible to all
    convert_A(0);

    for (int cc = 0; cc < 8; ++cc) {
        if (cc < 7) asm volatile("cp.async.wait_group 0;");   // stage cc+1 landed
        __syncthreads();   // publishes A(cc) STS + stage cc+1 cp.async data
        if (cc < 6) load_stage(cc + 2, (cc + 2) % 3);
        if (cc < 7) convert_A((cc + 1) % 3);

        const uint32_t base = sb + (cc % 3) * ST_STRIDE;
        const uint32_t aH = base, bH = base + OFF_B;

        #pragma unroll
        for (int ks = 0; ks < 4; ++ks) {
            uint32_t ah[2][4];
            const uint32_t axo = (uint32_t)(((achk + 2 * ks) ^ arow7) << 4);
            #pragma unroll
            for (int i = 0; i < 2; ++i)
                ldsm4(ah[i], aH + aRowB0 + (uint32_t)(i * 16 * 128) + axo);
            uint32_t bh[4][4];
            const uint32_t bxo = (uint32_t)(((bchk + 2 * ks) ^ brow7) << 4);
            #pragma unroll
            for (int p = 0; p < 4; ++p)
                ldsm4(bh[p], bH + bRowB0 + (uint32_t)(p * 16 * 128) + bxo);
            #pragma unroll
            for (int p = 0; p < 4; ++p) {
                #pragma unroll
                for (int i = 0; i < 2; ++i) {
                    mma16816(acc[i][2 * p],     ah[i], &bh[p][0]);
                    mma16816(acc[i][2 * p + 1], ah[i], &bh[p][2]);
                }
            }
        }
    }
    __syncthreads();   // protect smem reuse below

    // ---------------- epilogue: max over M (relu via 0-init) ---------------
    int* s_max = reinterpret_cast<int*>(smem);
    if (tid < 256) s_max[tid] = 0;
    __syncthreads();

    #pragma unroll
    for (int j = 0; j < 8; ++j) {
        float v0 = fmaxf(fmaxf(acc[0][j][0], acc[0][j][2]),
                         fmaxf(acc[1][j][0], acc[1][j][2]));
        float v1 = fmaxf(fmaxf(acc[0][j][1], acc[0][j][3]),
                         fmaxf(acc[1][j][1], acc[1][j][3]));
        #pragma unroll
        for (int off = 4; off < 32; off <<= 1) {
            v0 = fmaxf(v0, __shfl_xor_sync(0xffffffffu, v0, off));
            v1 = fmaxf(v1, __shfl_xor_sync(0xffffffffu, v1, off));
        }
        if (lane < 4) {
            int col = wn * 64 + j * 8 + lane * 2;
            atomicMax(&s_max[col],     __float_as_int(v0));
            atomicMax(&s_max[col + 1], __float_as_int(v1));
        }
    }
    __syncthreads();

    if (tid < 256) {
        // all candidates >= 0 vs 0-init: signed-int max == relu'd float max
        atomicMax(reinterpret_cast<int*>(out + (size_t)b * NK + n0 + tid), s_max[tid]);
    }
}

// ---------------- launch -----------------------------------------------------
extern "C" void kernel_launch(void* const* d_in, const int* in_sizes, int n_in,
                              void* d_out, int out_size) {
    const float* x  = (const float*)d_in[0];   // (B, C, L)
    const float* sh = (const float*)d_in[1];   // (C, K, S)
    float* out = (float*)d_out;                // (B, 1, K)

    cudaMemsetAsync(out, 0, (size_t)out_size * sizeof(float), 0);

    prep_kernel<<<768, 256>>>(x, sh);

    cudaFuncSetAttribute(gemm_kernel, cudaFuncAttributeMaxDynamicSharedMemorySize,
                         SMEM_BYTES);
    gemm_kernel<<<dim3(16, 2, 32), 512, SMEM_BYTES>>>(x, out);
}

// round 8
// speedup vs baseline: 1.1080x; 1.1080x over previous
#include <cuda_runtime.h>
#include <cuda_fp16.h>
#include <stdint.h>

#define NB 32
#define NC 8
#define NL 2048
#define NK 512
#define NS 64
#define NW (NL - NS + 1)   // 1985
#define MPAD 2048
#define KTOT 512           // NC * NS

// ---------------- device scratch (static, allocation-free) ----------------
__device__ __half g_A[(size_t)NB * MPAD * KTOT];   // 64 MB, [b][w][c*64+s]
__device__ __half g_B[(size_t)NK * KTOT];          // 512 KB, [k][c*64+s]

// ---------------- helpers ----------------
__device__ __forceinline__ uint32_t smem_u32(const void* p) {
    uint32_t a;
    asm("{ .reg .u64 t; cvta.to.shared.u64 t, %1; cvt.u32.u64 %0, t; }"
        : "=r"(a) : "l"(p));
    return a;
}

__device__ __forceinline__ void cp16(uint32_t dst, const void* src) {
    asm volatile("cp.async.cg.shared.global [%0], [%1], 16;" :: "r"(dst), "l"(src));
}

__device__ __forceinline__ void ldsm4(uint32_t* r, uint32_t addr) {
    asm volatile("ldmatrix.sync.aligned.m8n8.x4.shared.b16 {%0,%1,%2,%3}, [%4];"
                 : "=r"(r[0]), "=r"(r[1]), "=r"(r[2]), "=r"(r[3]) : "r"(addr));
}

__device__ __forceinline__ void mma16816(float* d, const uint32_t* a, const uint32_t* b) {
    asm volatile(
        "mma.sync.aligned.m16n8k16.row.col.f32.f16.f16.f32 "
        "{%0,%1,%2,%3}, {%4,%5,%6,%7}, {%8,%9}, {%0,%1,%2,%3};"
        : "+f"(d[0]), "+f"(d[1]), "+f"(d[2]), "+f"(d[3])
        : "r"(a[0]), "r"(a[1]), "r"(a[2]), "r"(a[3]), "r"(b[0]), "r"(b[1]));
}

// ---------------- Kernel 1: ONE-launch prep -------------------------------
// blocks [0,512):    B = fp16(sn_norm / 8), layout [k][c*64+s]
// blocks [512,4608): one (b, c, 128-w tile) each: window inv-norms from a
//                    192-float x slice, then A = fp16(x_window * inv).
__global__ __launch_bounds__(256) void prep_kernel(const float* __restrict__ x,
                                                   const float* __restrict__ sh) {
    __shared__ float xs[192];
    __shared__ float invs[128];
    const int tid = threadIdx.x;
    if (blockIdx.x < 512) {
        int gw   = (blockIdx.x * 256 + tid) >> 5;
        int lane = tid & 31;
        int c = gw / NK, k = gw % NK;
        const float* row = sh + (size_t)(c * NK + k) * NS;
        float v0 = row[lane], v1 = row[lane + 32];
        float ss = v0 * v0 + v1 * v1;
        #pragma unroll
        for (int o = 16; o > 0; o >>= 1) ss += __shfl_xor_sync(0xffffffffu, ss, o);
        float sc = 0.125f / fmaxf(sqrtf(ss), 1e-8f);
        size_t base = (size_t)k * KTOT + c * 64 + lane;
        g_B[base]      = __float2half(v0 * sc);
        g_B[base + 32] = __float2half(v1 * sc);
        return;
    }
    const int id = blockIdx.x - 512;       // 0..4095
    const int wt = id & 15;
    const int c  = (id >> 4) & 7;
    const int b  = id >> 7;
    const int w0 = wt * 128;

    if (tid < 192) {
        int j = w0 + tid;
        xs[tid] = (j < NL) ? x[((size_t)(b * NC + c)) * NL + j] : 0.f;
    }
    __syncthreads();
    if (tid < 128) {
        int w = w0 + tid;
        if (w < NW) {
            float ss = 0.f;
            #pragma unroll 16
            for (int s = 0; s < NS; ++s) { float v = xs[tid + s]; ss += v * v; }
            invs[tid] = 1.0f / fmaxf(sqrtf(ss), 1e-8f);
        } else {
            invs[tid] = 0.f;
        }
    }
    __syncthreads();
    #pragma unroll
    for (int it = 0; it < 4; ++it) {
        int idx = it * 256 + tid;           // 1024 16B-chunks: 128 rows x 8
        int r = idx >> 3, s0 = (idx & 7) * 8;
        float inv = invs[r];
        __half h[8];
        #pragma unroll
        for (int j = 0; j < 8; ++j) h[j] = __float2half(xs[r + s0 + j] * inv);
        size_t base = ((size_t)(b * MPAD + w0 + r)) * KTOT + c * 64 + s0;
        *reinterpret_cast<uint4*>(&g_A[base]) = *reinterpret_cast<uint4*>(h);
    }
}

// ---------------- Kernel 2: fp16 mma.sync GEMM + relu-max epilogue ---------
// Block tile M=128 x N=256, 256 threads (8 warps, 2x4), warp tile 64x64.
// K: 8 chunks of 64, 4-stage cp.async pipeline, one barrier per chunk.
#define NSTAGE 4
#define STAGE_BYTES 49152
#define OFF_B 16384
#define SMEM_BYTES (NSTAGE * STAGE_BYTES)   // 196608

__global__ __launch_bounds__(256, 1) void gemm_kernel(float* __restrict__ out) {
    extern __shared__ char smem[];
    const uint32_t sb = smem_u32(smem);
    const int tid = threadIdx.x;
    const int wid = tid >> 5, lane = tid & 31;
    const int m0 = blockIdx.x * 128, n0 = blockIdx.y * 256, b = blockIdx.z;

    const int wm = wid & 1, wn = wid >> 1;   // 2 x 4 warp grid

    const int t8 = lane >> 3, lr = lane & 7;
    const int arow = wm * 64 + (t8 & 1) * 8 + lr;   // + i*16, i<4
    const int achk = t8 >> 1;                        // + 2*ks
    const int brow = wn * 64 + (t8 >> 1) * 8 + lr;  // + p*16, p<4
    const int bchk = t8 & 1;                         // + 2*ks
    const int arow7 = arow & 7, brow7 = brow & 7;
    const uint32_t aRowB0 = (uint32_t)(arow * 128);
    const uint32_t bRowB0 = (uint32_t)(brow * 128);

    const __half* A0 = g_A + ((size_t)(b * MPAD + m0)) * KTOT;
    const __half* B0 = g_B + (size_t)n0 * KTOT;

    // stage loader: A 128x64 (16 KB) + B 256x64 (32 KB), 16B-chunk XOR swizzle
    auto load_stage = [&](int cc, int s) {
        const uint32_t base = sb + s * STAGE_BYTES;
        const __half* ga = A0 + cc * 64;
        const __half* gb = B0 + cc * 64;
        #pragma unroll
        for (int j = 0; j < 4; ++j) {        // A: 1024 chunks / 256 thr
            int i = j * 256 + tid;
            int row = i >> 3, c16 = i & 7;
            uint32_t so = (uint32_t)(row * 128 + ((c16 ^ (row & 7)) << 4));
            cp16(base + so, ga + (size_t)row * KTOT + c16 * 8);
        }
        #pragma unroll
        for (int j = 0; j < 8; ++j) {        // B: 2048 chunks / 256 thr
            int i = j * 256 + tid;
            int row = i >> 3, c16 = i & 7;
            uint32_t so = (uint32_t)(row * 128 + ((c16 ^ (row & 7)) << 4));
            cp16(base + OFF_B + so, gb + (size_t)row * KTOT + c16 * 8);
        }
        asm volatile("cp.async.commit_group;");
    };

    float acc[4][8][4];
    #pragma unroll
    for (int i = 0; i < 4; ++i)
        #pragma unroll
        for (int j = 0; j < 8; ++j)
            #pragma unroll
            for (int c = 0; c < 4; ++c) acc[i][j][c] = 0.f;

    load_stage(0, 0);
    load_stage(1, 1);
    load_stage(2, 2);

    for (int cc = 0; cc < 8; ++cc) {
        // wait until group cc has landed
        if (cc <= 5)      asm volatile("cp.async.wait_group 2;");
        else if (cc == 6) asm volatile("cp.async.wait_group 1;");
        else              asm volatile("cp.async.wait_group 0;");
        __syncthreads();   // all warps done with stage being overwritten
        if (cc < 5) load_stage(cc + 3, (cc + 3) % NSTAGE);

        const uint32_t base = sb + (cc % NSTAGE) * STAGE_BYTES;
        const uint32_t aH = base, bH = base + OFF_B;

        #pragma unroll
        for (int ks = 0; ks < 4; ++ks) {
            uint32_t ah[4][4];
            const uint32_t axo = (uint32_t)(((achk + 2 * ks) ^ arow7) << 4);
            #pragma unroll
            for (int i = 0; i < 4; ++i)
                ldsm4(ah[i], aH + aRowB0 + (uint32_t)(i * 16 * 128) + axo);
            uint32_t bh[4][4];
            const uint32_t bxo = (uint32_t)(((bchk + 2 * ks) ^ brow7) << 4);
            #pragma unroll
            for (int p = 0; p < 4; ++p)
                ldsm4(bh[p], bH + bRowB0 + (uint32_t)(p * 16 * 128) + bxo);
            #pragma unroll
            for (int p = 0; p < 4; ++p) {
                #pragma unroll
                for (int i = 0; i < 4; ++i) {
                    mma16816(acc[i][2 * p],     ah[i], &bh[p][0]);
                    mma16816(acc[i][2 * p + 1], ah[i], &bh[p][2]);
                }
            }
        }
    }
    __syncthreads();   // protect smem reuse below

    // ---------------- epilogue: max over M (relu via 0-init) ---------------
    int* s_max = reinterpret_cast<int*>(smem);
    s_max[tid] = 0;
    __syncthreads();

    #pragma unroll
    for (int j = 0; j < 8; ++j) {
        float v0 = fmaxf(fmaxf(acc[0][j][0], acc[0][j][2]),
                         fmaxf(acc[1][j][0], acc[1][j][2]));
        v0 = fmaxf(v0, fmaxf(fmaxf(acc[2][j][0], acc[2][j][2]),
                             fmaxf(acc[3][j][0], acc[3][j][2])));
        float v1 = fmaxf(fmaxf(acc[0][j][1], acc[0][j][3]),
                         fmaxf(acc[1][j][1], acc[1][j][3]));
        v1 = fmaxf(v1, fmaxf(fmaxf(acc[2][j][1], acc[2][j][3]),
                             fmaxf(acc[3][j][1], acc[3][j][3])));
        #pragma unroll
        for (int off = 4; off < 32; off <<= 1) {
            v0 = fmaxf(v0, __shfl_xor_sync(0xffffffffu, v0, off));
            v1 = fmaxf(v1, __shfl_xor_sync(0xffffffffu, v1, off));
        }
        if (lane < 4) {
            int col = wn * 64 + j * 8 + lane * 2;
            atomicMax(&s_max[col],     __float_as_int(v0));
            atomicMax(&s_max[col + 1], __float_as_int(v1));
        }
    }
    __syncthreads();

    // all candidates >= 0 vs 0-init: signed-int max == relu'd float max
    atomicMax(reinterpret_cast<int*>(out + (size_t)b * NK + n0 + tid), s_max[tid]);
}

// ---------------- launch -----------------------------------------------------
extern "C" void kernel_launch(void* const* d_in, const int* in_sizes, int n_in,
                              void* d_out, int out_size) {
    const float* x  = (const float*)d_in[0];   // (B, C, L)
    const float* sh = (const float*)d_in[1];   // (C, K, S)
    float* out = (float*)d_out;                // (B, 1, K)

    cudaMemsetAsync(out, 0, (size_t)out_size * sizeof(float), 0);

    prep_kernel<<<4608, 256>>>(x, sh);

    cudaFuncSetAttribute(gemm_kernel, cudaFuncAttributeMaxDynamicSharedMemorySize,
                         SMEM_BYTES);
    gemm_kernel<<<dim3(16, 2, 32), 256, SMEM_BYTES>>>(out);
}

// round 9
// speedup vs baseline: 1.1817x; 1.0665x over previous
#include <cuda_runtime.h>
#include <cuda_fp16.h>
#include <stdint.h>

#define NB 32
#define NC 8
#define NL 2048
#define NK 512
#define NS 64
#define NW (NL - NS + 1)   // 1985
#define MPAD 2048
#define KTOT 512           // NC * NS

// ---------------- device scratch (static, allocation-free) ----------------
__device__ __half g_A[(size_t)NB * MPAD * KTOT];   // 64 MB, [b][w][c*64+s]
__device__ __half g_B[(size_t)NK * KTOT];          // 512 KB, [k][c*64+s]

// ---------------- helpers ----------------
__device__ __forceinline__ uint32_t smem_u32(const void* p) {
    uint32_t a;
    asm("{ .reg .u64 t; cvta.to.shared.u64 t, %1; cvt.u32.u64 %0, t; }"
        : "=r"(a) : "l"(p));
    return a;
}

__device__ __forceinline__ void cp16(uint32_t dst, const void* src) {
    asm volatile("cp.async.cg.shared.global [%0], [%1], 16;" :: "r"(dst), "l"(src));
}

__device__ __forceinline__ void ldsm4(uint32_t* r, uint32_t addr) {
    asm volatile("ldmatrix.sync.aligned.m8n8.x4.shared.b16 {%0,%1,%2,%3}, [%4];"
                 : "=r"(r[0]), "=r"(r[1]), "=r"(r[2]), "=r"(r[3]) : "r"(addr));
}

__device__ __forceinline__ void mma16816(float* d, const uint32_t* a, const uint32_t* b) {
    asm volatile(
        "mma.sync.aligned.m16n8k16.row.col.f32.f16.f16.f32 "
        "{%0,%1,%2,%3}, {%4,%5,%6,%7}, {%8,%9}, {%0,%1,%2,%3};"
        : "+f"(d[0]), "+f"(d[1]), "+f"(d[2]), "+f"(d[3])
        : "r"(a[0]), "r"(a[1]), "r"(a[2]), "r"(a[3]), "r"(b[0]), "r"(b[1]));
}

// ---------------- Kernel 1: ONE-launch prep -------------------------------
// blocks [0,512):    B = fp16(sn_norm / 8), layout [k][c*64+s]
// blocks [512,4608): one (b, c, 128-w tile) each: window inv-norms from a
//                    192-float x slice, then A = fp16(x_window * inv).
__global__ __launch_bounds__(256) void prep_kernel(const float* __restrict__ x,
                                                   const float* __restrict__ sh) {
    __shared__ float xs[192];
    __shared__ float invs[128];
    const int tid = threadIdx.x;
    if (blockIdx.x < 512) {
        int gw   = (blockIdx.x * 256 + tid) >> 5;
        int lane = tid & 31;
        int c = gw / NK, k = gw % NK;
        const float* row = sh + (size_t)(c * NK + k) * NS;
        float v0 = row[lane], v1 = row[lane + 32];
        float ss = v0 * v0 + v1 * v1;
        #pragma unroll
        for (int o = 16; o > 0; o >>= 1) ss += __shfl_xor_sync(0xffffffffu, ss, o);
        float sc = 0.125f / fmaxf(sqrtf(ss), 1e-8f);
        size_t base = (size_t)k * KTOT + c * 64 + lane;
        g_B[base]      = __float2half(v0 * sc);
        g_B[base + 32] = __float2half(v1 * sc);
        return;
    }
    const int id = blockIdx.x - 512;       // 0..4095
    const int wt = id & 15;
    const int c  = (id >> 4) & 7;
    const int b  = id >> 7;
    const int w0 = wt * 128;

    if (tid < 192) {
        int j = w0 + tid;
        xs[tid] = (j < NL) ? x[((size_t)(b * NC + c)) * NL + j] : 0.f;
    }
    __syncthreads();
    if (tid < 128) {
        int w = w0 + tid;
        if (w < NW) {
            float ss = 0.f;
            #pragma unroll 16
            for (int s = 0; s < NS; ++s) { float v = xs[tid + s]; ss += v * v; }
            invs[tid] = 1.0f / fmaxf(sqrtf(ss), 1e-8f);
        } else {
            invs[tid] = 0.f;
        }
    }
    __syncthreads();
    #pragma unroll
    for (int it = 0; it < 4; ++it) {
        int idx = it * 256 + tid;           // 1024 16B-chunks: 128 rows x 8
        int r = idx >> 3, s0 = (idx & 7) * 8;
        float inv = invs[r];
        __half h[8];
        #pragma unroll
        for (int j = 0; j < 8; ++j) h[j] = __float2half(xs[r + s0 + j] * inv);
        size_t base = ((size_t)(b * MPAD + w0 + r)) * KTOT + c * 64 + s0;
        *reinterpret_cast<uint4*>(&g_A[base]) = *reinterpret_cast<uint4*>(h);
    }
}

// ---------------- Kernel 2: fp16 mma.sync GEMM + relu-max epilogue ---------
// Block tile M=128 x N=128, 128 threads (4 warps, 2x2), warp tile 64x64.
// 2 CTAs/SM (decoupled barriers). K: 8 chunks of 64, 3-stage cp.async.
#define NSTAGE 3
#define STAGE_BYTES 32768
#define OFF_B 16384
#define SMEM_BYTES (NSTAGE * STAGE_BYTES)   // 98304 per CTA

__global__ __launch_bounds__(128, 2) void gemm_kernel(float* __restrict__ out) {
    extern __shared__ char smem[];
    const uint32_t sb = smem_u32(smem);
    const int tid = threadIdx.x;
    const int wid = tid >> 5, lane = tid & 31;
    const int m0 = blockIdx.x * 128, n0 = blockIdx.y * 128, b = blockIdx.z;

    const int wm = wid & 1, wn = wid >> 1;   // 2 x 2 warp grid

    const int t8 = lane >> 3, lr = lane & 7;
    const int arow = wm * 64 + (t8 & 1) * 8 + lr;   // + i*16, i<4
    const int achk = t8 >> 1;                        // + 2*ks
    const int brow = wn * 64 + (t8 >> 1) * 8 + lr;  // + p*16, p<4
    const int bchk = t8 & 1;                         // + 2*ks
    const int arow7 = arow & 7, brow7 = brow & 7;
    const uint32_t aRowB0 = (uint32_t)(arow * 128);
    const uint32_t bRowB0 = (uint32_t)(brow * 128);

    const __half* A0 = g_A + ((size_t)(b * MPAD + m0)) * KTOT;
    const __half* B0 = g_B + (size_t)n0 * KTOT;

    // stage loader: A 128x64 (16 KB) + B 128x64 (16 KB), 16B-chunk XOR swizzle
    auto load_stage = [&](int cc, int s) {
        const uint32_t base = sb + s * STAGE_BYTES;
        const __half* ga = A0 + cc * 64;
        const __half* gb = B0 + cc * 64;
        #pragma unroll
        for (int j = 0; j < 8; ++j) {        // A: 1024 chunks / 128 thr
            int i = j * 128 + tid;
            int row = i >> 3, c16 = i & 7;
            uint32_t so = (uint32_t)(row * 128 + ((c16 ^ (row & 7)) << 4));
            cp16(base + so, ga + (size_t)row * KTOT + c16 * 8);
        }
        #pragma unroll
        for (int j = 0; j < 8; ++j) {        // B: 1024 chunks / 128 thr
            int i = j * 128 + tid;
            int row = i >> 3, c16 = i & 7;
            uint32_t so = (uint32_t)(row * 128 + ((c16 ^ (row & 7)) << 4));
            cp16(base + OFF_B + so, gb + (size_t)row * KTOT + c16 * 8);
        }
        asm volatile("cp.async.commit_group;");
    };

    float acc[4][8][4];
    #pragma unroll
    for (int i = 0; i < 4; ++i)
        #pragma unroll
        for (int j = 0; j < 8; ++j)
            #pragma unroll
            for (int c = 0; c < 4; ++c) acc[i][j][c] = 0.f;

    load_stage(0, 0);
    load_stage(1, 1);

    for (int cc = 0; cc < 8; ++cc) {
        if (cc < 7) asm volatile("cp.async.wait_group 1;");
        else        asm volatile("cp.async.wait_group 0;");
        __syncthreads();   // stage cc ready for all; stage being overwritten free
        if (cc < 6) load_stage(cc + 2, (cc + 2) % NSTAGE);

        const uint32_t base = sb + (cc % NSTAGE) * STAGE_BYTES;
        const uint32_t aH = base, bH = base + OFF_B;

        #pragma unroll
        for (int ks = 0; ks < 4; ++ks) {
            uint32_t ah[4][4];
            const uint32_t axo = (uint32_t)(((achk + 2 * ks) ^ arow7) << 4);
            #pragma unroll
            for (int i = 0; i < 4; ++i)
                ldsm4(ah[i], aH + aRowB0 + (uint32_t)(i * 16 * 128) + axo);
            uint32_t bh[4][4];
            const uint32_t bxo = (uint32_t)(((bchk + 2 * ks) ^ brow7) << 4);
            #pragma unroll
            for (int p = 0; p < 4; ++p)
                ldsm4(bh[p], bH + bRowB0 + (uint32_t)(p * 16 * 128) + bxo);
            #pragma unroll
            for (int p = 0; p < 4; ++p) {
                #pragma unroll
                for (int i = 0; i < 4; ++i) {
                    mma16816(acc[i][2 * p],     ah[i], &bh[p][0]);
                    mma16816(acc[i][2 * p + 1], ah[i], &bh[p][2]);
                }
            }
        }
    }
    __syncthreads();   // protect smem reuse below

    // ---------------- epilogue: max over M (relu via 0-init) ---------------
    int* s_max = reinterpret_cast<int*>(smem);
    s_max[tid] = 0;
    __syncthreads();

    #pragma unroll
    for (int j = 0; j < 8; ++j) {
        float v0 = fmaxf(fmaxf(acc[0][j][0], acc[0][j][2]),
                         fmaxf(acc[1][j][0], acc[1][j][2]));
        v0 = fmaxf(v0, fmaxf(fmaxf(acc[2][j][0], acc[2][j][2]),
                             fmaxf(acc[3][j][0], acc[3][j][2])));
        float v1 = fmaxf(fmaxf(acc[0][j][1], acc[0][j][3]),
                         fmaxf(acc[1][j][1], acc[1][j][3]));
        v1 = fmaxf(v1, fmaxf(fmaxf(acc[2][j][1], acc[2][j][3]),
                             fmaxf(acc[3][j][1], acc[3][j][3])));
        #pragma unroll
        for (int off = 4; off < 32; off <<= 1) {
            v0 = fmaxf(v0, __shfl_xor_sync(0xffffffffu, v0, off));
            v1 = fmaxf(v1, __shfl_xor_sync(0xffffffffu, v1, off));
        }
        if (lane < 4) {
            int col = wn * 64 + j * 8 + lane * 2;
            atomicMax(&s_max[col],     __float_as_int(v0));
            atomicMax(&s_max[col + 1], __float_as_int(v1));
        }
    }
    __syncthreads();

    // all candidates >= 0 vs 0-init: signed-int max == relu'd float max
    atomicMax(reinterpret_cast<int*>(out + (size_t)b * NK + n0 + tid), s_max[tid]);
}

// ---------------- launch -----------------------------------------------------
extern "C" void kernel_launch(void* const* d_in, const int* in_sizes, int n_in,
                              void* d_out, int out_size) {
    const float* x  = (const float*)d_in[0];   // (B, C, L)
    const float* sh = (const float*)d_in[1];   // (C, K, S)
    float* out = (float*)d_out;                // (B, 1, K)

    cudaMemsetAsync(out, 0, (size_t)out_size * sizeof(float), 0);

    prep_kernel<<<4608, 256>>>(x, sh);

    cudaFuncSetAttribute(gemm_kernel, cudaFuncAttributeMaxDynamicSharedMemorySize,
                         SMEM_BYTES);
    gemm_kernel<<<dim3(16, 4, 32), 128, SMEM_BYTES>>>(out);
}